// round 3
// baseline (speedup 1.0000x reference)
#include <cuda_runtime.h>
#include <cuda_fp16.h>
#include <cstdint>

static constexpr int NROWS = 16384;
static constexpr int DDIM  = 1024;

// ---------------- device scratch (allocation-free rule: __device__ globals) ----
__device__ __half g_xh[(size_t)NROWS * DDIM];   // x in fp16, [m][k]            (32 MB)
__device__ __half g_qt[(size_t)DDIM  * DDIM];   // Q^T fp16: g_qt[n*D+k]=Q[k*D+n] (2 MB)

// ---------------- helpers ------------------------------------------------------
__device__ __forceinline__ uint32_t smem_u32(const void* p) {
    uint32_t a;
    asm("{ .reg .u64 t; cvta.to.shared.u64 t, %1; cvt.u32.u64 %0, t; }" : "=r"(a) : "l"(p));
    return a;
}

#define CP16(dst, src) \
    asm volatile("cp.async.cg.shared.global [%0], [%1], 16;" :: "r"(dst), "l"(src))
#define CP_COMMIT() asm volatile("cp.async.commit_group;")

#define LDSM4(r, addr) \
    asm volatile("ldmatrix.sync.aligned.m8n8.x4.shared.b16 {%0,%1,%2,%3}, [%4];" \
        : "=r"((r)[0]), "=r"((r)[1]), "=r"((r)[2]), "=r"((r)[3]) : "r"(addr))

#define MMA16816(d, a, b0, b1) \
    asm volatile("mma.sync.aligned.m16n8k16.row.col.f32.f16.f16.f32 " \
        "{%0,%1,%2,%3}, {%4,%5,%6,%7}, {%8,%9}, {%0,%1,%2,%3};" \
        : "+f"((d)[0]), "+f"((d)[1]), "+f"((d)[2]), "+f"((d)[3]) \
        : "r"((a)[0]), "r"((a)[1]), "r"((a)[2]), "r"((a)[3]), "r"(b0), "r"(b1))

// ---------------- pre-pass kernels ---------------------------------------------
__global__ void cvt_x_kernel(const float* __restrict__ x) {
    size_t i = ((size_t)blockIdx.x * blockDim.x + threadIdx.x) * 8;
    float4 a = *reinterpret_cast<const float4*>(x + i);
    float4 b = *reinterpret_cast<const float4*>(x + i + 4);
    __half2 h0 = __floats2half2_rn(a.x, a.y);
    __half2 h1 = __floats2half2_rn(a.z, a.w);
    __half2 h2 = __floats2half2_rn(b.x, b.y);
    __half2 h3 = __floats2half2_rn(b.z, b.w);
    uint4 v;
    v.x = *reinterpret_cast<uint32_t*>(&h0);
    v.y = *reinterpret_cast<uint32_t*>(&h1);
    v.z = *reinterpret_cast<uint32_t*>(&h2);
    v.w = *reinterpret_cast<uint32_t*>(&h3);
    *reinterpret_cast<uint4*>(&g_xh[i]) = v;
}

__global__ void cvt_qt_kernel(const float* __restrict__ Q) {
    __shared__ float t[32][33];
    int tx = threadIdx.x, ty = threadIdx.y;
    int bx = blockIdx.x * 32, by = blockIdx.y * 32;
    for (int i = 0; i < 4; i++)
        t[ty + i * 8][tx] = Q[(size_t)(by + ty + i * 8) * DDIM + bx + tx];
    __syncthreads();
    for (int i = 0; i < 4; i++)
        g_qt[(size_t)(bx + ty + i * 8) * DDIM + by + tx] = __float2half(t[tx][ty + i * 8]);
}

// ---------------- main fused GEMM + diag epilogue ------------------------------
// CTA: 512 threads (16 warps, 4M x 4N). Tile M=128, N=256, K=32. 4 cp.async stages.
// SMEM per stage: A 128x32 f16 rows padded to 80B (10240B), B 256x32 f16 (20480B).
static constexpr int A_STRIDE    = 80;            // 64B data + 16B pad (conflict-free ldmatrix)
static constexpr int STAGE_A     = 128 * A_STRIDE;            // 10240
static constexpr int STAGE_B     = 256 * A_STRIDE;            // 20480
static constexpr int STAGE_BYTES = STAGE_A + STAGE_B;         // 30720
static constexpr int BVEC_OFF    = 4 * STAGE_BYTES;           // 122880, 1024 floats
static constexpr int ROWACC_OFF  = BVEC_OFF + 4096;           // 126976, 128 floats
static constexpr int SMEM_TOTAL  = ROWACC_OFF + 512;          // 127488

__global__ void __launch_bounds__(512, 1) quad_mma_kernel(
    const float* __restrict__ x, const float* __restrict__ bv,
    const float* __restrict__ cv, float* __restrict__ out)
{
    extern __shared__ char smem[];
    const uint32_t sb = smem_u32(smem);
    const int tid  = threadIdx.x;
    const int lane = tid & 31;
    const int wid  = tid >> 5;
    const int mwarp = wid & 3;        // 32-row block within 128
    const int nwarp = wid >> 2;       // 64-col block within 256
    const int m0 = blockIdx.x * 128;

    float* bS     = reinterpret_cast<float*>(smem + BVEC_OFF);
    float* rowacc = reinterpret_cast<float*>(smem + ROWACC_OFF);
    if (tid < 128) rowacc[tid] = 0.f;
    for (int i = tid; i < 1024; i += 512) bS[i] = bv[i];

    // ldmatrix lane-address components (x4: 4 groups of 8 lanes)
    const int rowoff = (lane & 7) + ((lane >> 3) & 1) * 8;  // row within 16-row block
    const int chsel  = lane >> 4;                           // k-chunk within k16

    // cp.async issue for iteration `it` (it = ntile*32 + ktile)
    auto issue = [&](int it) {
        const int nt = it >> 5, kt = it & 31;
        const int k0 = kt * 32, n0 = nt * 256;
        const uint32_t As = sb + (it & 3) * STAGE_BYTES;
        const uint32_t Bs = As + STAGE_A;
        {   // A: 512 x 16B chunks, one per thread
            const int row = tid >> 2, ch = tid & 3;
            CP16(As + row * A_STRIDE + ch * 16,
                 (const void*)&g_xh[(size_t)(m0 + row) * DDIM + k0 + ch * 8]);
        }
        #pragma unroll
        for (int r = 0; r < 2; r++) {   // B: 1024 x 16B chunks, two per thread
            const int idx = tid + r * 512;
            const int row = idx >> 2, ch = idx & 3;
            CP16(Bs + row * A_STRIDE + ch * 16,
                 (const void*)&g_qt[(size_t)(n0 + row) * DDIM + k0 + ch * 8]);
        }
        CP_COMMIT();
    };

    issue(0); issue(1); issue(2);

    float rp[4] = {0.f, 0.f, 0.f, 0.f};   // persistent per-row partials
    float acc[2][8][4];

    for (int it = 0; it < 128; it++) {
        const int kt = it & 31;
        if (kt == 0) {
            #pragma unroll
            for (int mb = 0; mb < 2; mb++)
                #pragma unroll
                for (int nb = 0; nb < 8; nb++)
                    #pragma unroll
                    for (int q = 0; q < 4; q++) acc[mb][nb][q] = 0.f;
        }

        asm volatile("cp.async.wait_group 2;" ::: "memory");
        __syncthreads();
        if (it + 3 < 128) issue(it + 3);

        const uint32_t As = sb + (it & 3) * STAGE_BYTES;
        const uint32_t Bs = As + STAGE_A;

        #pragma unroll
        for (int k16 = 0; k16 < 2; k16++) {
            uint32_t a[2][4], bf[4][4];
            #pragma unroll
            for (int mb = 0; mb < 2; mb++)
                LDSM4(a[mb], As + (mwarp * 32 + mb * 16 + rowoff) * A_STRIDE
                                + (k16 * 2 + chsel) * 16);
            #pragma unroll
            for (int j = 0; j < 4; j++)
                LDSM4(bf[j], Bs + (nwarp * 64 + j * 16 + rowoff) * A_STRIDE
                                + (k16 * 2 + chsel) * 16);
            #pragma unroll
            for (int mb = 0; mb < 2; mb++)
                #pragma unroll
                for (int j = 0; j < 4; j++)
                    #pragma unroll
                    for (int h = 0; h < 2; h++)
                        MMA16816(acc[mb][j * 2 + h], a[mb], bf[j][h], bf[j][h + 2]);
        }

        if (kt == 31) {
            // epilogue for this ntile: rp += (Z + b) .* x  (x in fp32)
            const int n0 = (it >> 5) * 256;
            #pragma unroll
            for (int mb = 0; mb < 2; mb++) {
                const int r0 = m0 + mwarp * 32 + mb * 16 + (lane >> 2);
                #pragma unroll
                for (int nb = 0; nb < 8; nb++) {
                    const int n = n0 + nwarp * 64 + nb * 8 + 2 * (lane & 3);
                    float2 x0 = *reinterpret_cast<const float2*>(&x[(size_t)r0 * DDIM + n]);
                    float2 x1 = *reinterpret_cast<const float2*>(&x[(size_t)(r0 + 8) * DDIM + n]);
                    float2 bb = *reinterpret_cast<float2*>(&bS[n]);
                    rp[mb * 2 + 0] += (acc[mb][nb][0] + bb.x) * x0.x
                                    + (acc[mb][nb][1] + bb.y) * x0.y;
                    rp[mb * 2 + 1] += (acc[mb][nb][2] + bb.x) * x1.x
                                    + (acc[mb][nb][3] + bb.y) * x1.y;
                }
            }
        }
    }

    asm volatile("cp.async.wait_group 0;" ::: "memory");
    __syncthreads();

    const int rbase = mwarp * 32 + (lane >> 2);
    atomicAdd(&rowacc[rbase +  0], rp[0]);
    atomicAdd(&rowacc[rbase +  8], rp[1]);
    atomicAdd(&rowacc[rbase + 16], rp[2]);
    atomicAdd(&rowacc[rbase + 24], rp[3]);
    __syncthreads();
    if (tid < 128) out[m0 + tid] = rowacc[tid] + cv[0];
}

// ---------------- launch -------------------------------------------------------
extern "C" void kernel_launch(void* const* d_in, const int* in_sizes, int n_in,
                              void* d_out, int out_size) {
    const float* x = (const float*)d_in[0];   // [16384, 1024]
    const float* Q = (const float*)d_in[1];   // [1024, 1024]
    const float* b = (const float*)d_in[2];   // [1024]
    const float* c = (const float*)d_in[3];   // [1]
    float* out = (float*)d_out;               // [16384, 1]

    cudaFuncSetAttribute(quad_mma_kernel,
                         cudaFuncAttributeMaxDynamicSharedMemorySize, SMEM_TOTAL);

    cvt_x_kernel<<<(NROWS * DDIM) / (256 * 8), 256>>>(x);
    cvt_qt_kernel<<<dim3(DDIM / 32, DDIM / 32), dim3(32, 8)>>>(Q);
    quad_mma_kernel<<<NROWS / 128, 512, SMEM_TOTAL>>>(x, b, c, out);
}

// round 4
// speedup vs baseline: 1.1824x; 1.1824x over previous
#include <cuda_runtime.h>
#include <cuda_fp16.h>
#include <cstdint>

static constexpr int NROWS = 16384;
static constexpr int DDIM  = 1024;

// ---------------- device scratch -----------------------------------------------
__device__ __half g_xh[(size_t)NROWS * DDIM];   // x fp16 [m][k]            (32 MB)
__device__ __half g_qt[(size_t)DDIM  * DDIM];   // Q^T fp16: [n][k]          (2 MB)

// ---------------- helpers ------------------------------------------------------
__device__ __forceinline__ uint32_t smem_u32(const void* p) {
    uint32_t a;
    asm("{ .reg .u64 t; cvta.to.shared.u64 t, %1; cvt.u32.u64 %0, t; }" : "=r"(a) : "l"(p));
    return a;
}

#define CP16(dst, src) \
    asm volatile("cp.async.cg.shared.global [%0], [%1], 16;" :: "r"(dst), "l"(src))
#define CP_COMMIT() asm volatile("cp.async.commit_group;")

#define LDSM4(r, addr) \
    asm volatile("ldmatrix.sync.aligned.m8n8.x4.shared.b16 {%0,%1,%2,%3}, [%4];" \
        : "=r"((r)[0]), "=r"((r)[1]), "=r"((r)[2]), "=r"((r)[3]) : "r"(addr))

#define MMA16816(d, a, b0, b1) \
    asm volatile("mma.sync.aligned.m16n8k16.row.col.f32.f16.f16.f32 " \
        "{%0,%1,%2,%3}, {%4,%5,%6,%7}, {%8,%9}, {%0,%1,%2,%3};" \
        : "+f"((d)[0]), "+f"((d)[1]), "+f"((d)[2]), "+f"((d)[3]) \
        : "r"((a)[0]), "r"((a)[1]), "r"((a)[2]), "r"((a)[3]), "r"(b0), "r"(b1))

// ---------------- pre-pass kernels ---------------------------------------------
__global__ void cvt_x_kernel(const float* __restrict__ x) {
    size_t i = ((size_t)blockIdx.x * blockDim.x + threadIdx.x) * 8;
    float4 a = *reinterpret_cast<const float4*>(x + i);
    float4 b = *reinterpret_cast<const float4*>(x + i + 4);
    __half2 h0 = __floats2half2_rn(a.x, a.y);
    __half2 h1 = __floats2half2_rn(a.z, a.w);
    __half2 h2 = __floats2half2_rn(b.x, b.y);
    __half2 h3 = __floats2half2_rn(b.z, b.w);
    uint4 v;
    v.x = *reinterpret_cast<uint32_t*>(&h0);
    v.y = *reinterpret_cast<uint32_t*>(&h1);
    v.z = *reinterpret_cast<uint32_t*>(&h2);
    v.w = *reinterpret_cast<uint32_t*>(&h3);
    *reinterpret_cast<uint4*>(&g_xh[i]) = v;
}

__global__ void cvt_qt_kernel(const float* __restrict__ Q) {
    __shared__ float t[32][33];
    int tx = threadIdx.x, ty = threadIdx.y;
    int bx = blockIdx.x * 32, by = blockIdx.y * 32;
    for (int i = 0; i < 4; i++)
        t[ty + i * 8][tx] = Q[(size_t)(by + ty + i * 8) * DDIM + bx + tx];
    __syncthreads();
    for (int i = 0; i < 4; i++)
        g_qt[(size_t)(bx + ty + i * 8) * DDIM + by + tx] = __float2half(t[tx][ty + i * 8]);
}

// ---------------- main fused GEMM + diag epilogue ------------------------------
// 512 threads (16 warps, 4M x 4N). Tile M=128, N=256, K=64. 3 cp.async stages.
static constexpr int A_STRIDE    = 144;                       // 128B data + 16B pad
static constexpr int STAGE_A     = 128 * A_STRIDE;            // 18432
static constexpr int STAGE_B     = 256 * A_STRIDE;            // 36864
static constexpr int STAGE_BYTES = STAGE_A + STAGE_B;         // 55296
static constexpr int BVEC_OFF    = 3 * STAGE_BYTES;           // 165888, 1024 floats
static constexpr int ROWACC_OFF  = BVEC_OFF + 4096;           // 169984, 128 floats
static constexpr int SMEM_TOTAL  = ROWACC_OFF + 512;          // 170496

static constexpr int NITER = 64;                              // 4 n-passes x 16 k-tiles

__global__ void __launch_bounds__(512, 1) quad_mma_kernel(
    const float* __restrict__ x, const float* __restrict__ bv,
    const float* __restrict__ cv, float* __restrict__ out)
{
    extern __shared__ char smem[];
    const uint32_t sb = smem_u32(smem);
    const int tid  = threadIdx.x;
    const int lane = tid & 31;
    const int wid  = tid >> 5;
    const int mwarp = wid & 3;        // 32-row block within 128
    const int nwarp = wid >> 2;       // 64-col block within 256
    const int m0 = blockIdx.x * 128;

    float* bS     = reinterpret_cast<float*>(smem + BVEC_OFF);
    float* rowacc = reinterpret_cast<float*>(smem + ROWACC_OFF);
    if (tid < 128) rowacc[tid] = 0.f;
    for (int i = tid; i < 1024; i += 512) bS[i] = bv[i];

    const int rowoff = (lane & 7) + ((lane >> 3) & 1) * 8;  // row within 16-row block
    const int chsel  = lane >> 4;                           // 16B chunk within k16

    // cp.async issue for iteration `it` (it = ntile*16 + ktile, K-tile = 64)
    auto issue = [&](int it) {
        const int nt = it >> 4, kt = it & 15;
        const int k0 = kt * 64, n0 = nt * 256;
        const uint32_t As = sb + (it % 3) * STAGE_BYTES;
        const uint32_t Bs = As + STAGE_A;
        #pragma unroll
        for (int r = 0; r < 2; r++) {   // A: 1024 x 16B chunks
            const int idx = tid + r * 512;
            const int row = idx >> 3, ch = idx & 7;
            CP16(As + row * A_STRIDE + ch * 16,
                 (const void*)&g_xh[(size_t)(m0 + row) * DDIM + k0 + ch * 8]);
        }
        #pragma unroll
        for (int r = 0; r < 4; r++) {   // B: 2048 x 16B chunks
            const int idx = tid + r * 512;
            const int row = idx >> 3, ch = idx & 7;
            CP16(Bs + row * A_STRIDE + ch * 16,
                 (const void*)&g_qt[(size_t)(n0 + row) * DDIM + k0 + ch * 8]);
        }
        CP_COMMIT();
    };

    issue(0); issue(1);

    float rp[4] = {0.f, 0.f, 0.f, 0.f};
    float acc[2][8][4];

    for (int it = 0; it < NITER; it++) {
        const int kt = it & 15;
        if (kt == 0) {
            #pragma unroll
            for (int mb = 0; mb < 2; mb++)
                #pragma unroll
                for (int nb = 0; nb < 8; nb++)
                    #pragma unroll
                    for (int q = 0; q < 4; q++) acc[mb][nb][q] = 0.f;
        }

        if (it < NITER - 2) {
            issue(it + 2);
            asm volatile("cp.async.wait_group 1;" ::: "memory");
        } else if (it == NITER - 2) {
            asm volatile("cp.async.wait_group 1;" ::: "memory");
        } else {
            asm volatile("cp.async.wait_group 0;" ::: "memory");
        }
        __syncthreads();

        const uint32_t As = sb + (it % 3) * STAGE_BYTES;
        const uint32_t Bs = As + STAGE_A;

        #pragma unroll
        for (int k16 = 0; k16 < 4; k16++) {
            uint32_t a[2][4];
            #pragma unroll
            for (int mb = 0; mb < 2; mb++)
                LDSM4(a[mb], As + (mwarp * 32 + mb * 16 + rowoff) * A_STRIDE
                                + (k16 * 2 + chsel) * 16);
            #pragma unroll
            for (int jh = 0; jh < 2; jh++) {          // N in two halves: frag regs small
                uint32_t bf[2][4];
                #pragma unroll
                for (int jj = 0; jj < 2; jj++)
                    LDSM4(bf[jj], Bs + (nwarp * 64 + (jh * 2 + jj) * 16 + rowoff) * A_STRIDE
                                     + (k16 * 2 + chsel) * 16);
                #pragma unroll
                for (int mb = 0; mb < 2; mb++)
                    #pragma unroll
                    for (int jj = 0; jj < 2; jj++)
                        #pragma unroll
                        for (int h = 0; h < 2; h++)
                            MMA16816(acc[mb][(jh * 2 + jj) * 2 + h],
                                     a[mb], bf[jj][h], bf[jj][h + 2]);
            }
        }

        if (kt == 15) {
            // epilogue for this ntile: rp += (Z + b) .* x  (x read in fp32)
            const int n0 = (it >> 4) * 256;
            #pragma unroll
            for (int mb = 0; mb < 2; mb++) {
                const int r0 = m0 + mwarp * 32 + mb * 16 + (lane >> 2);
                #pragma unroll
                for (int nb = 0; nb < 8; nb++) {
                    const int n = n0 + nwarp * 64 + nb * 8 + 2 * (lane & 3);
                    float2 x0 = *reinterpret_cast<const float2*>(&x[(size_t)r0 * DDIM + n]);
                    float2 x1 = *reinterpret_cast<const float2*>(&x[(size_t)(r0 + 8) * DDIM + n]);
                    float2 bb = *reinterpret_cast<float2*>(&bS[n]);
                    rp[mb * 2 + 0] += (acc[mb][nb][0] + bb.x) * x0.x
                                    + (acc[mb][nb][1] + bb.y) * x0.y;
                    rp[mb * 2 + 1] += (acc[mb][nb][2] + bb.x) * x1.x
                                    + (acc[mb][nb][3] + bb.y) * x1.y;
                }
            }
        }
    }

    __syncthreads();
    const int rbase = mwarp * 32 + (lane >> 2);
    atomicAdd(&rowacc[rbase +  0], rp[0]);
    atomicAdd(&rowacc[rbase +  8], rp[1]);
    atomicAdd(&rowacc[rbase + 16], rp[2]);
    atomicAdd(&rowacc[rbase + 24], rp[3]);
    __syncthreads();
    if (tid < 128) out[m0 + tid] = rowacc[tid] + cv[0];
}

// ---------------- launch -------------------------------------------------------
extern "C" void kernel_launch(void* const* d_in, const int* in_sizes, int n_in,
                              void* d_out, int out_size) {
    const float* x = (const float*)d_in[0];   // [16384, 1024]
    const float* Q = (const float*)d_in[1];   // [1024, 1024]
    const float* b = (const float*)d_in[2];   // [1024]
    const float* c = (const float*)d_in[3];   // [1]
    float* out = (float*)d_out;               // [16384, 1]

    cudaFuncSetAttribute(quad_mma_kernel,
                         cudaFuncAttributeMaxDynamicSharedMemorySize, SMEM_TOTAL);

    cvt_x_kernel<<<(NROWS * DDIM) / (256 * 8), 256>>>(x);
    cvt_qt_kernel<<<dim3(DDIM / 32, DDIM / 32), dim3(32, 8)>>>(Q);
    quad_mma_kernel<<<NROWS / 128, 512, SMEM_TOTAL>>>(x, b, c, out);
}

// round 7
// speedup vs baseline: 1.1858x; 1.0029x over previous
#include <cuda_runtime.h>
#include <cuda_fp16.h>
#include <cstdint>

static constexpr int NROWS = 16384;
static constexpr int DDIM  = 1024;

// ---------------- device scratch -----------------------------------------------
__device__ __half g_qt[(size_t)DDIM * DDIM];   // Q^T fp16: g_qt[n*D+k]=Q[k*D+n] (2 MB)

// ---------------- helpers ------------------------------------------------------
__device__ __forceinline__ uint32_t smem_u32(const void* p) {
    uint32_t a;
    asm("{ .reg .u64 t; cvta.to.shared.u64 t, %1; cvt.u32.u64 %0, t; }" : "=r"(a) : "l"(p));
    return a;
}

#define CP16(dst, src) \
    asm volatile("cp.async.cg.shared.global [%0], [%1], 16;" :: "r"(dst), "l"(src))
#define CP_COMMIT() asm volatile("cp.async.commit_group;")

#define LDSM4(r, addr) \
    asm volatile("ldmatrix.sync.aligned.m8n8.x4.shared.b16 {%0,%1,%2,%3}, [%4];" \
        : "=r"((r)[0]), "=r"((r)[1]), "=r"((r)[2]), "=r"((r)[3]) : "r"(addr))

#define LDS64F(f0, f1, addr) \
    asm volatile("ld.shared.v2.f32 {%0,%1}, [%2];" : "=f"(f0), "=f"(f1) : "r"(addr))

#define MMA16816(d, a, b0, b1) \
    asm volatile("mma.sync.aligned.m16n8k16.row.col.f32.f16.f16.f32 " \
        "{%0,%1,%2,%3}, {%4,%5,%6,%7}, {%8,%9}, {%0,%1,%2,%3};" \
        : "+f"((d)[0]), "+f"((d)[1]), "+f"((d)[2]), "+f"((d)[3]) \
        : "r"((a)[0]), "r"((a)[1]), "r"((a)[2]), "r"((a)[3]), "r"(b0), "r"(b1))

__device__ __forceinline__ uint32_t packh2(float lo, float hi) {
    __half2 h = __floats2half2_rn(lo, hi);
    return *reinterpret_cast<uint32_t*>(&h);
}

// ---------------- pre-pass: Q^T in fp16 ----------------------------------------
__global__ void cvt_qt_kernel(const float* __restrict__ Q) {
    __shared__ float t[32][33];
    int tx = threadIdx.x, ty = threadIdx.y;
    int bx = blockIdx.x * 32, by = blockIdx.y * 32;
    for (int i = 0; i < 4; i++)
        t[ty + i * 8][tx] = Q[(size_t)(by + ty + i * 8) * DDIM + bx + tx];
    __syncthreads();
    for (int i = 0; i < 4; i++)
        g_qt[(size_t)(bx + ty + i * 8) * DDIM + by + tx] = __float2half(t[tx][ty + i * 8]);
}

// ---------------- main fused GEMM + diag epilogue ------------------------------
// 512 threads (16 warps, 4M x 4N). Tile M=128, N=256, K=64. 3 cp.async stages.
// A staged in fp32 (rows padded to 288B), converted to f16 fragments in regs.
// B staged in f16 (144B rows) for ldmatrix.
static constexpr int A_STRIDE    = 288;                       // 256B data + 32B pad
static constexpr int B_STRIDE    = 144;                       // 128B data + 16B pad
static constexpr int STAGE_A     = 128 * A_STRIDE;            // 36864
static constexpr int STAGE_B     = 256 * B_STRIDE;            // 36864
static constexpr int STAGE_BYTES = STAGE_A + STAGE_B;         // 73728
static constexpr int BVEC_OFF    = 3 * STAGE_BYTES;           // 221184, 1024 floats
static constexpr int RED_OFF     = BVEC_OFF + 4096;           // 225280, 4x128 floats
static constexpr int SMEM_TOTAL  = RED_OFF + 2048;            // 227328

static constexpr int NITER = 64;                              // 4 n-passes x 16 k-tiles

__global__ void __launch_bounds__(512, 1) quad_mma_kernel(
    const float* __restrict__ x, const float* __restrict__ bv,
    const float* __restrict__ cv, float* __restrict__ out)
{
    extern __shared__ char smem[];
    const uint32_t sb = smem_u32(smem);
    const int tid  = threadIdx.x;
    const int lane = tid & 31;
    const int wid  = tid >> 5;
    const int mwarp = wid & 3;        // 32-row block within 128
    const int nwarp = wid >> 2;       // 64-col block within 256
    const int m0 = blockIdx.x * 128;

    float* bS  = reinterpret_cast<float*>(smem + BVEC_OFF);
    float* red = reinterpret_cast<float*>(smem + RED_OFF);
    for (int i = tid; i < 1024; i += 512) bS[i] = bv[i];

    const int rowoff = (lane & 7) + ((lane >> 3) & 1) * 8;  // B ldmatrix row
    const int chsel  = lane >> 4;                           // B ldmatrix 16B chunk
    const int arow   = mwarp * 32 + (lane >> 2);            // A frag row (+mb*16, +8)
    const int acol   = (lane & 3) * 2;                      // A frag col (+k16*16, +8)

    // cp.async issue for iteration `it` (it = ntile*16 + ktile, K-tile = 64)
    auto issue = [&](int it) {
        const int nt = it >> 4, kt = it & 15;
        const int k0 = kt * 64, n0 = nt * 256;
        const uint32_t As = sb + (it % 3) * STAGE_BYTES;
        const uint32_t Bs = As + STAGE_A;
        #pragma unroll
        for (int r = 0; r < 4; r++) {   // A fp32: 2048 x 16B chunks
            const int idx = tid + r * 512;
            const int row = idx >> 4, ch = idx & 15;
            CP16(As + row * A_STRIDE + ch * 16,
                 (const void*)&x[(size_t)(m0 + row) * DDIM + k0 + ch * 4]);
        }
        #pragma unroll
        for (int r = 0; r < 4; r++) {   // B f16: 2048 x 16B chunks
            const int idx = tid + r * 512;
            const int row = idx >> 3, ch = idx & 7;
            CP16(Bs + row * B_STRIDE + ch * 16,
                 (const void*)&g_qt[(size_t)(n0 + row) * DDIM + k0 + ch * 8]);
        }
        CP_COMMIT();
    };

    issue(0); issue(1);

    float rp[4] = {0.f, 0.f, 0.f, 0.f};
    float acc[2][8][4];

    for (int it = 0; it < NITER; it++) {
        const int kt = it & 15;
        if (kt == 0) {
            #pragma unroll
            for (int mb = 0; mb < 2; mb++)
                #pragma unroll
                for (int nb = 0; nb < 8; nb++)
                    #pragma unroll
                    for (int q = 0; q < 4; q++) acc[mb][nb][q] = 0.f;
        }

        // RACE-SAFE ORDER: wait -> barrier -> issue into (it+2)%3 == (it-1)%3,
        // whose readers are all provably past the barrier.
        if (it == NITER - 1) {
            asm volatile("cp.async.wait_group 0;" ::: "memory");
        } else {
            asm volatile("cp.async.wait_group 1;" ::: "memory");
        }
        __syncthreads();
        if (it + 2 < NITER) issue(it + 2);

        const uint32_t As = sb + (it % 3) * STAGE_BYTES;
        const uint32_t Bs = As + STAGE_A;

        #pragma unroll
        for (int k16 = 0; k16 < 4; k16++) {
            // A fragments: fp32 LDS.64 + convert (no x prepass needed)
            uint32_t a[2][4];
            #pragma unroll
            for (int mb = 0; mb < 2; mb++) {
                const uint32_t base = As + (arow + mb * 16) * A_STRIDE
                                         + (k16 * 16 + acol) * 4;
                float f0, f1, f2, f3, f4, f5, f6, f7;
                LDS64F(f0, f1, base);
                LDS64F(f2, f3, base + 8 * A_STRIDE);
                LDS64F(f4, f5, base + 32);               // cols +8
                LDS64F(f6, f7, base + 8 * A_STRIDE + 32);
                a[mb][0] = packh2(f0, f1);
                a[mb][1] = packh2(f2, f3);
                a[mb][2] = packh2(f4, f5);
                a[mb][3] = packh2(f6, f7);
            }
            #pragma unroll
            for (int jh = 0; jh < 2; jh++) {
                uint32_t bf[2][4];
                #pragma unroll
                for (int jj = 0; jj < 2; jj++)
                    LDSM4(bf[jj], Bs + (nwarp * 64 + (jh * 2 + jj) * 16 + rowoff) * B_STRIDE
                                     + (k16 * 2 + chsel) * 16);
                #pragma unroll
                for (int mb = 0; mb < 2; mb++)
                    #pragma unroll
                    for (int jj = 0; jj < 2; jj++)
                        #pragma unroll
                        for (int h = 0; h < 2; h++)
                            MMA16816(acc[mb][(jh * 2 + jj) * 2 + h],
                                     a[mb], bf[jj][h], bf[jj][h + 2]);
            }
        }

        if (kt == 15) {
            // epilogue for this ntile: rp += (Z + b) .* x  (x read in fp32)
            const int n0 = (it >> 4) * 256;
            #pragma unroll
            for (int mb = 0; mb < 2; mb++) {
                const int r0 = m0 + mwarp * 32 + mb * 16 + (lane >> 2);
                #pragma unroll
                for (int nb = 0; nb < 8; nb++) {
                    const int n = n0 + nwarp * 64 + nb * 8 + 2 * (lane & 3);
                    float2 x0 = *reinterpret_cast<const float2*>(&x[(size_t)r0 * DDIM + n]);
                    float2 x1 = *reinterpret_cast<const float2*>(&x[(size_t)(r0 + 8) * DDIM + n]);
                    float2 bb = *reinterpret_cast<float2*>(&bS[n]);
                    rp[mb * 2 + 0] += (acc[mb][nb][0] + bb.x) * x0.x
                                    + (acc[mb][nb][1] + bb.y) * x0.y;
                    rp[mb * 2 + 1] += (acc[mb][nb][2] + bb.x) * x1.x
                                    + (acc[mb][nb][3] + bb.y) * x1.y;
                }
            }
        }
    }

    // ---- deterministic reduction: quad shfl (fixed order) -> smem -> fixed 4-way sum
    #pragma unroll
    for (int i = 0; i < 4; i++) {
        rp[i] += __shfl_xor_sync(0xFFFFFFFFu, rp[i], 1);
        rp[i] += __shfl_xor_sync(0xFFFFFFFFu, rp[i], 2);
    }
    __syncthreads();
    if ((lane & 3) == 0) {
        const int rbase = mwarp * 32 + (lane >> 2);
        red[nwarp * 128 + rbase +  0] = rp[0];
        red[nwarp * 128 + rbase +  8] = rp[1];
        red[nwarp * 128 + rbase + 16] = rp[2];
        red[nwarp * 128 + rbase + 24] = rp[3];
    }
    __syncthreads();
    if (tid < 128)
        out[m0 + tid] = ((red[tid] + red[128 + tid])
                       + (red[256 + tid] + red[384 + tid])) + cv[0];
}

// ---------------- launch -------------------------------------------------------
extern "C" void kernel_launch(void* const* d_in, const int* in_sizes, int n_in,
                              void* d_out, int out_size) {
    const float* x = (const float*)d_in[0];   // [16384, 1024]
    const float* Q = (const float*)d_in[1];   // [1024, 1024]
    const float* b = (const float*)d_in[2];   // [1024]
    const float* c = (const float*)d_in[3];   // [1]
    float* out = (float*)d_out;               // [16384, 1]

    cudaFuncSetAttribute(quad_mma_kernel,
                         cudaFuncAttributeMaxDynamicSharedMemorySize, SMEM_TOTAL);

    cvt_qt_kernel<<<dim3(DDIM / 32, DDIM / 32), dim3(32, 8)>>>(Q);
    quad_mma_kernel<<<NROWS / 128, 512, SMEM_TOTAL>>>(x, b, c, out);
}